// round 6
// baseline (speedup 1.0000x reference)
#include <cuda_runtime.h>
#include <math.h>

#define NN   50000
#define DD   128
#define SS   25
#define TM   64
#define NBLK ((NN + TM - 1) / TM)   // 782

typedef unsigned long long u64;

// ---------------- scratch (device globals; no allocation allowed) ----------
__device__ float g_h1[NN * DD];
__device__ float g_x [NN * DD];
__device__ float g_xn[NN * DD];
__device__ float g_h2[NN * DD];
__device__ float g_psum  [NBLK * DD];
__device__ float g_psumsq[NBLK * DD];
__device__ float g_scale[DD];
__device__ float g_shift[DD];

// ---------------- packed f32x2 helpers -------------------------------------
__device__ __forceinline__ void fma2(u64& d, u64 a, u64 b) {
    asm("fma.rn.f32x2 %0, %1, %2, %0;" : "+l"(d) : "l"(a), "l"(b));
}
__device__ __forceinline__ float2 upk2(u64 v) {
    float2 r;
    asm("mov.b64 {%0, %1}, %2;" : "=f"(r.x), "=f"(r.y) : "l"(v));
    return r;
}
__device__ __forceinline__ u64 lo64(const float4& v) {
    return *(const u64*)(&v.x);
}
__device__ __forceinline__ u64 hi64(const float4& v) {
    return *(const u64*)(&v.z);
}

// Swizzled transposed-weight addressing (float index), K = row length.
// phys(n,k) = n*K + 4*(((k>>2) + (n>>2)) & (K/4-1)) + (k&3)
__device__ __forceinline__ int widx(int n, int k, int K) {
    return n * K + ((((k >> 2) + (n >> 2)) & ((K >> 2) - 1)) << 2) + (k & 3);
}

// ---------------------------------------------------------------------------
// O[rows,128] = relu(A[rows,128] @ W[128,128] + b)
// 256 threads, TM=64 tile. W transposed+swizzled in smem.
// Thread (ty,tx): rows ty*8..+7, cols tx*4..+3. K-packed f32x2, zero movs.
// ---------------------------------------------------------------------------
__global__ __launch_bounds__(256, 2) void gemm128_relu(
    const float* __restrict__ A, const float* __restrict__ W,
    const float* __restrict__ bias, float* __restrict__ O, int nrows)
{
    extern __shared__ float sm[];
    float* Wt = sm;                 // 128*128 floats (swizzled, Wt[n][k])
    float* As = sm + 128 * 128;     // 64*128  floats

    const int tid = threadIdx.x;
    const int tileBase = blockIdx.x * TM;

    // stage W transposed+swizzled: Wt[n][k] = W[k][n]
    const float4* Wg4 = (const float4*)W;
    #pragma unroll
    for (int i = 0; i < 16; i++) {
        int idx4 = tid + i * 256;            // 4096 float4
        int k  = idx4 >> 5;
        int n0 = (idx4 & 31) * 4;
        float4 v = Wg4[idx4];
        Wt[widx(n0 + 0, k, 128)] = v.x;
        Wt[widx(n0 + 1, k, 128)] = v.y;
        Wt[widx(n0 + 2, k, 128)] = v.z;
        Wt[widx(n0 + 3, k, 128)] = v.w;
    }

    // stage A tile
    #pragma unroll
    for (int i = 0; i < 8; i++) {
        int idx = tid + i * 256;             // 2048 float4
        int r = idx >> 5, c = idx & 31;
        int row = tileBase + r;
        float4 v = make_float4(0.f, 0.f, 0.f, 0.f);
        if (row < nrows) v = ((const float4*)(A + (size_t)row * DD))[c];
        ((float4*)(As + r * DD))[c] = v;
    }
    __syncthreads();

    const int ty = tid >> 5, tx = tid & 31;
    u64 acc[8][4];
    #pragma unroll
    for (int r = 0; r < 8; r++)
        #pragma unroll
        for (int c = 0; c < 4; c++) acc[r][c] = 0ull;

    const float* Abase = As + (ty * 8) * DD;
    // lane's 4 weight rows: n = tx*4 + c; n>>2 == tx for c in 0..3
    const float* Wl = Wt + (tx * 4) * 128;

    #pragma unroll 2
    for (int k = 0; k < 128; k += 4) {
        int slot = (((k >> 2) + tx) & 31) << 2;   // swizzled float4 slot
        float4 w[4];
        #pragma unroll
        for (int c = 0; c < 4; c++)
            w[c] = *(const float4*)(Wl + c * 128 + slot);
        #pragma unroll
        for (int r = 0; r < 8; r++) {
            float4 a = *(const float4*)(Abase + r * DD + k);
            u64 aL = lo64(a), aH = hi64(a);
            #pragma unroll
            for (int c = 0; c < 4; c++) {
                fma2(acc[r][c], aL, lo64(w[c]));
                fma2(acc[r][c], aH, hi64(w[c]));
            }
        }
    }

    float4 b4 = ((const float4*)bias)[tx];
    #pragma unroll
    for (int r = 0; r < 8; r++) {
        int row = tileBase + ty * 8 + r;
        if (row < nrows) {
            float2 p0 = upk2(acc[r][0]);
            float2 p1 = upk2(acc[r][1]);
            float2 p2 = upk2(acc[r][2]);
            float2 p3 = upk2(acc[r][3]);
            float4 o;
            o.x = fmaxf(p0.x + p0.y + b4.x, 0.f);
            o.y = fmaxf(p1.x + p1.y + b4.y, 0.f);
            o.z = fmaxf(p2.x + p2.y + b4.z, 0.f);
            o.w = fmaxf(p3.x + p3.y + b4.w, 0.f);
            ((float4*)(O + (size_t)row * DD))[tx] = o;
        }
    }
}

// ---------------------------------------------------------------------------
// Fused: agg[n,:] = max_{s<25} H[idx[n,s],:], then
//        O = act( concat(A0, agg) @ W[256,128] + b ), optional BN partials.
// W transposed+swizzled in smem (row length 256). K-packed f32x2.
// ---------------------------------------------------------------------------
template<bool RELU, bool BNSTATS>
__global__ __launch_bounds__(256) void gather_gemm256(
    const float* __restrict__ A0, const float* __restrict__ H,
    const int* __restrict__ nidx, const float* __restrict__ W,
    const float* __restrict__ bias, float* __restrict__ O, int nrows)
{
    extern __shared__ float sm[];
    float* Wt = sm;                 // 128*256 floats (128 KB, swizzled)
    float* As = sm + 128 * 256;     // 64*256  floats (64 KB)

    const int tid = threadIdx.x;
    const int tileBase = blockIdx.x * TM;
    const int ty = tid >> 5, tx = tid & 31;

    // stage W transposed+swizzled: Wt[n][k] = W[k][n], W is [256][128]
    const float4* Wg4 = (const float4*)W;
    #pragma unroll
    for (int i = 0; i < 32; i++) {
        int idx4 = tid + i * 256;            // 8192 float4
        int k  = idx4 >> 5;                  // 0..255
        int n0 = (idx4 & 31) * 4;
        float4 v = Wg4[idx4];
        Wt[widx(n0 + 0, k, 256)] = v.x;
        Wt[widx(n0 + 1, k, 256)] = v.y;
        Wt[widx(n0 + 2, k, 256)] = v.z;
        Wt[widx(n0 + 3, k, 256)] = v.w;
    }

    // self features into As[r][0..127]
    #pragma unroll
    for (int i = 0; i < 8; i++) {
        int idx = tid + i * 256;
        int r = idx >> 5, c = idx & 31;
        int row = tileBase + r;
        float4 v = make_float4(0.f, 0.f, 0.f, 0.f);
        if (row < nrows) v = ((const float4*)(A0 + (size_t)row * DD))[c];
        ((float4*)(As + r * 256))[c] = v;
    }

    // gather-max into As[r][128..255]  (H >= 0, init 0 exact)
    #pragma unroll
    for (int r = 0; r < 8; r++) {
        int row = tileBase + ty * 8 + r;
        float4 m = make_float4(0.f, 0.f, 0.f, 0.f);
        if (row < nrows) {
            const int* ip = nidx + (size_t)row * SS;
            int myi = (tx < SS) ? ip[tx] : 0;
            #pragma unroll
            for (int s = 0; s < SS; s++) {
                int j = __shfl_sync(0xffffffffu, myi, s);
                float4 v = ((const float4*)(H + (size_t)j * DD))[tx];
                m.x = fmaxf(m.x, v.x);
                m.y = fmaxf(m.y, v.y);
                m.z = fmaxf(m.z, v.z);
                m.w = fmaxf(m.w, v.w);
            }
        }
        ((float4*)(As + (ty * 8 + r) * 256 + 128))[tx] = m;
    }
    __syncthreads();

    u64 acc[8][4];
    #pragma unroll
    for (int r = 0; r < 8; r++)
        #pragma unroll
        for (int c = 0; c < 4; c++) acc[r][c] = 0ull;

    const float* Abase = As + (ty * 8) * 256;
    const float* Wl = Wt + (tx * 4) * 256;

    #pragma unroll 2
    for (int k = 0; k < 256; k += 4) {
        int slot = (((k >> 2) + tx) & 63) << 2;
        float4 w[4];
        #pragma unroll
        for (int c = 0; c < 4; c++)
            w[c] = *(const float4*)(Wl + c * 256 + slot);
        #pragma unroll
        for (int r = 0; r < 8; r++) {
            float4 a = *(const float4*)(Abase + r * 256 + k);
            u64 aL = lo64(a), aH = hi64(a);
            #pragma unroll
            for (int c = 0; c < 4; c++) {
                fma2(acc[r][c], aL, lo64(w[c]));
                fma2(acc[r][c], aH, hi64(w[c]));
            }
        }
    }

    float4 b4 = ((const float4*)bias)[tx];
    float cs[4] = {0.f, 0.f, 0.f, 0.f};
    float cq[4] = {0.f, 0.f, 0.f, 0.f};
    #pragma unroll
    for (int r = 0; r < 8; r++) {
        int row = tileBase + ty * 8 + r;
        if (row < nrows) {
            float2 p0 = upk2(acc[r][0]);
            float2 p1 = upk2(acc[r][1]);
            float2 p2 = upk2(acc[r][2]);
            float2 p3 = upk2(acc[r][3]);
            float4 o;
            o.x = p0.x + p0.y + b4.x;
            o.y = p1.x + p1.y + b4.y;
            o.z = p2.x + p2.y + b4.z;
            o.w = p3.x + p3.y + b4.w;
            if (RELU) {
                o.x = fmaxf(o.x, 0.f); o.y = fmaxf(o.y, 0.f);
                o.z = fmaxf(o.z, 0.f); o.w = fmaxf(o.w, 0.f);
            }
            ((float4*)(O + (size_t)row * DD))[tx] = o;
            if (BNSTATS) {
                cs[0] += o.x; cs[1] += o.y; cs[2] += o.z; cs[3] += o.w;
                cq[0] += o.x * o.x; cq[1] += o.y * o.y;
                cq[2] += o.z * o.z; cq[3] += o.w * o.w;
            }
        }
    }

    if (BNSTATS) {
        __syncthreads();               // done reading smem; reuse for reduction
        float* red = As;
        #pragma unroll
        for (int c = 0; c < 4; c++) {
            red[ty * 128 + tx * 4 + c]        = cs[c];
            red[1024 + ty * 128 + tx * 4 + c] = cq[c];
        }
        __syncthreads();
        if (tid < 128) {
            float s = 0.f, q = 0.f;
            #pragma unroll
            for (int w = 0; w < 8; w++) {
                s += red[w * 128 + tid];
                q += red[1024 + w * 128 + tid];
            }
            g_psum  [blockIdx.x * DD + tid] = s;
            g_psumsq[blockIdx.x * DD + tid] = q;
        }
    }
}

// ---------------------------------------------------------------------------
__global__ __launch_bounds__(1024) void bn_finalize(
    const float* __restrict__ gamma, const float* __restrict__ beta)
{
    __shared__ float rs[1024], rq[1024];
    const int t = threadIdx.x;
    const int col = t & 127, part = t >> 7;

    float s = 0.f, q = 0.f;
    for (int i = part; i < NBLK; i += 8) {
        s += g_psum  [i * DD + col];
        q += g_psumsq[i * DD + col];
    }
    rs[part * 128 + col] = s;
    rq[part * 128 + col] = q;
    __syncthreads();

    if (t < 128) {
        float ss = 0.f, qq = 0.f;
        #pragma unroll
        for (int p = 0; p < 8; p++) {
            ss += rs[p * 128 + t];
            qq += rq[p * 128 + t];
        }
        float mean = ss * (1.0f / NN);
        float var  = qq * (1.0f / NN) - mean * mean;
        float sc   = gamma[t] * rsqrtf(var + 1e-5f);
        g_scale[t] = sc;
        g_shift[t] = beta[t] - mean * sc;
    }
}

// ---------------------------------------------------------------------------
__global__ __launch_bounds__(256) void bn_rownorm(
    const float* __restrict__ X, float* __restrict__ XN, int nrows)
{
    const int ty = threadIdx.x >> 5, tx = threadIdx.x & 31;
    const int row = blockIdx.x * 8 + ty;
    if (row >= nrows) return;

    float4 v  = ((const float4*)(X + (size_t)row * DD))[tx];
    float4 sc = ((const float4*)g_scale)[tx];
    float4 sh = ((const float4*)g_shift)[tx];
    v.x = fmaf(v.x, sc.x, sh.x);
    v.y = fmaf(v.y, sc.y, sh.y);
    v.z = fmaf(v.z, sc.z, sh.z);
    v.w = fmaf(v.w, sc.w, sh.w);

    float ss = v.x * v.x + v.y * v.y + v.z * v.z + v.w * v.w;
    #pragma unroll
    for (int off = 16; off > 0; off >>= 1)
        ss += __shfl_xor_sync(0xffffffffu, ss, off);

    float inv = 1.0f / (sqrtf(ss) + 1e-6f);
    v.x *= inv; v.y *= inv; v.z *= inv; v.w *= inv;
    ((float4*)(XN + (size_t)row * DD))[tx] = v;
}

// ---------------------------------------------------------------------------
extern "C" void kernel_launch(void* const* d_in, const int* in_sizes, int n_in,
                              void* d_out, int out_size)
{
    const float* features = (const float*)d_in[0];
    const int*   idx1     = (const int*)  d_in[1];
    const int*   idx2     = (const int*)  d_in[2];
    const float* agg1_W   = (const float*)d_in[3];
    const float* agg1_b   = (const float*)d_in[4];
    const float* fc1_W    = (const float*)d_in[5];
    const float* fc1_b    = (const float*)d_in[6];
    const float* agg2_W   = (const float*)d_in[7];
    const float* agg2_b   = (const float*)d_in[8];
    const float* fc2_W    = (const float*)d_in[9];
    const float* fc2_b    = (const float*)d_in[10];
    const float* gamma    = (const float*)d_in[11];
    const float* beta     = (const float*)d_in[12];
    float* out = (float*)d_out;

    const int smem128 = (128 * 128 + TM * 128) * (int)sizeof(float);  //  98304
    const int smem256 = (128 * 256 + TM * 256) * (int)sizeof(float);  // 196608
    cudaFuncSetAttribute(gemm128_relu,
        cudaFuncAttributeMaxDynamicSharedMemorySize, smem128);
    cudaFuncSetAttribute(gather_gemm256<true, true>,
        cudaFuncAttributeMaxDynamicSharedMemorySize, smem256);
    cudaFuncSetAttribute(gather_gemm256<false, false>,
        cudaFuncAttributeMaxDynamicSharedMemorySize, smem256);

    float *h1, *x, *xn, *h2;
    cudaGetSymbolAddress((void**)&h1, g_h1);
    cudaGetSymbolAddress((void**)&x,  g_x);
    cudaGetSymbolAddress((void**)&xn, g_xn);
    cudaGetSymbolAddress((void**)&h2, g_h2);

    // ---- layer 1 ----
    gemm128_relu<<<NBLK, 256, smem128>>>(features, agg1_W, agg1_b, h1, NN);
    gather_gemm256<true, true><<<NBLK, 256, smem256>>>(
        features, h1, idx1, fc1_W, fc1_b, x, NN);
    bn_finalize<<<1, 1024>>>(gamma, beta);
    bn_rownorm<<<(NN + 7) / 8, 256>>>(x, xn, NN);

    // ---- layer 2 ----
    gemm128_relu<<<NBLK, 256, smem128>>>(xn, agg2_W, agg2_b, h2, NN);
    gather_gemm256<false, false><<<NBLK, 256, smem256>>>(
        xn, h2, idx2, fc2_W, fc2_b, out, NN);
}

// round 8
// speedup vs baseline: 1.0058x; 1.0058x over previous
#include <cuda_runtime.h>
#include <math.h>

#define NN   50000
#define DD   128
#define SS   25
#define TM   64
#define NBLK ((NN + TM - 1) / TM)   // 782

typedef unsigned long long u64;

// ---------------- scratch (device globals; no allocation allowed) ----------
__device__ float g_h1[NN * DD];
__device__ float g_x [NN * DD];
__device__ float g_xn[NN * DD];
__device__ float g_h2[NN * DD];
__device__ float g_psum  [NBLK * DD];
__device__ float g_psumsq[NBLK * DD];
__device__ float g_scale[DD];
__device__ float g_shift[DD];

// ---------------- packed f32x2 helpers -------------------------------------
__device__ __forceinline__ void fma2(u64& d, u64 a, u64 b) {
    asm("fma.rn.f32x2 %0, %1, %2, %0;" : "+l"(d) : "l"(a), "l"(b));
}
__device__ __forceinline__ float2 upk2(u64 v) {
    float2 r;
    asm("mov.b64 {%0, %1}, %2;" : "=f"(r.x), "=f"(r.y) : "l"(v));
    return r;
}
__device__ __forceinline__ u64 lo64(const float4& v) {
    return *(const u64*)(&v.x);
}
__device__ __forceinline__ u64 hi64(const float4& v) {
    return *(const u64*)(&v.z);
}

// Swizzled transposed-weight addressing (float index), K = row length.
// phys(n,k) = n*K + 4*(((k>>2) + (n>>2)) & (K/4-1)) + (k&3)
__device__ __forceinline__ int widx(int n, int k, int K) {
    return n * K + ((((k >> 2) + (n >> 2)) & ((K >> 2) - 1)) << 2) + (k & 3);
}

// ---------------------------------------------------------------------------
// O[rows,128] = relu(A[rows,128] @ W[128,128] + b)
// 256 threads, TM=64 tile. W transposed+swizzled in smem.
// Thread (ty,tx): rows ty*8..+7, cols tx*4..+3. K-packed f32x2, zero movs.
// ---------------------------------------------------------------------------
__global__ __launch_bounds__(256, 2) void gemm128_relu(
    const float* __restrict__ A, const float* __restrict__ W,
    const float* __restrict__ bias, float* __restrict__ O, int nrows)
{
    extern __shared__ float sm[];
    float* Wt = sm;                 // 128*128 floats (swizzled, Wt[n][k])
    float* As = sm + 128 * 128;     // 64*128  floats

    const int tid = threadIdx.x;
    const int tileBase = blockIdx.x * TM;

    // stage W transposed+swizzled: Wt[n][k] = W[k][n]
    const float4* Wg4 = (const float4*)W;
    #pragma unroll
    for (int i = 0; i < 16; i++) {
        int idx4 = tid + i * 256;            // 4096 float4
        int k  = idx4 >> 5;
        int n0 = (idx4 & 31) * 4;
        float4 v = Wg4[idx4];
        Wt[widx(n0 + 0, k, 128)] = v.x;
        Wt[widx(n0 + 1, k, 128)] = v.y;
        Wt[widx(n0 + 2, k, 128)] = v.z;
        Wt[widx(n0 + 3, k, 128)] = v.w;
    }

    // stage A tile
    #pragma unroll
    for (int i = 0; i < 8; i++) {
        int idx = tid + i * 256;             // 2048 float4
        int r = idx >> 5, c = idx & 31;
        int row = tileBase + r;
        float4 v = make_float4(0.f, 0.f, 0.f, 0.f);
        if (row < nrows) v = ((const float4*)(A + (size_t)row * DD))[c];
        ((float4*)(As + r * DD))[c] = v;
    }
    __syncthreads();

    const int ty = tid >> 5, tx = tid & 31;
    u64 acc[8][4];
    #pragma unroll
    for (int r = 0; r < 8; r++)
        #pragma unroll
        for (int c = 0; c < 4; c++) acc[r][c] = 0ull;

    const float* Abase = As + (ty * 8) * DD;
    // lane's 4 weight rows: n = tx*4 + c; n>>2 == tx for c in 0..3
    const float* Wl = Wt + (tx * 4) * 128;

    #pragma unroll 2
    for (int k = 0; k < 128; k += 4) {
        int slot = (((k >> 2) + tx) & 31) << 2;   // swizzled float4 slot
        float4 w[4];
        #pragma unroll
        for (int c = 0; c < 4; c++)
            w[c] = *(const float4*)(Wl + c * 128 + slot);
        #pragma unroll
        for (int r = 0; r < 8; r++) {
            float4 a = *(const float4*)(Abase + r * DD + k);
            u64 aL = lo64(a), aH = hi64(a);
            #pragma unroll
            for (int c = 0; c < 4; c++) {
                fma2(acc[r][c], aL, lo64(w[c]));
                fma2(acc[r][c], aH, hi64(w[c]));
            }
        }
    }

    float4 b4 = ((const float4*)bias)[tx];
    #pragma unroll
    for (int r = 0; r < 8; r++) {
        int row = tileBase + ty * 8 + r;
        if (row < nrows) {
            float2 p0 = upk2(acc[r][0]);
            float2 p1 = upk2(acc[r][1]);
            float2 p2 = upk2(acc[r][2]);
            float2 p3 = upk2(acc[r][3]);
            float4 o;
            o.x = fmaxf(p0.x + p0.y + b4.x, 0.f);
            o.y = fmaxf(p1.x + p1.y + b4.y, 0.f);
            o.z = fmaxf(p2.x + p2.y + b4.z, 0.f);
            o.w = fmaxf(p3.x + p3.y + b4.w, 0.f);
            ((float4*)(O + (size_t)row * DD))[tx] = o;
        }
    }
}

// ---------------------------------------------------------------------------
// Fused: agg[n,:] = max_{s<25} H[idx[n,s],:], then
//        O = act( concat(A0, agg) @ W[256,128] + b ), optional BN partials.
// W transposed+swizzled in smem (row length 256). K-packed f32x2.
// ---------------------------------------------------------------------------
template<bool RELU, bool BNSTATS>
__global__ __launch_bounds__(256) void gather_gemm256(
    const float* __restrict__ A0, const float* __restrict__ H,
    const int* __restrict__ nidx, const float* __restrict__ W,
    const float* __restrict__ bias, float* __restrict__ O, int nrows)
{
    extern __shared__ float sm[];
    float* Wt = sm;                 // 128*256 floats (128 KB, swizzled)
    float* As = sm + 128 * 256;     // 64*256  floats (64 KB)

    const int tid = threadIdx.x;
    const int tileBase = blockIdx.x * TM;
    const int ty = tid >> 5, tx = tid & 31;

    // stage W transposed+swizzled: Wt[n][k] = W[k][n], W is [256][128]
    const float4* Wg4 = (const float4*)W;
    #pragma unroll
    for (int i = 0; i < 32; i++) {
        int idx4 = tid + i * 256;            // 8192 float4
        int k  = idx4 >> 5;                  // 0..255
        int n0 = (idx4 & 31) * 4;
        float4 v = Wg4[idx4];
        Wt[widx(n0 + 0, k, 256)] = v.x;
        Wt[widx(n0 + 1, k, 256)] = v.y;
        Wt[widx(n0 + 2, k, 256)] = v.z;
        Wt[widx(n0 + 3, k, 256)] = v.w;
    }

    // self features into As[r][0..127]
    #pragma unroll
    for (int i = 0; i < 8; i++) {
        int idx = tid + i * 256;
        int r = idx >> 5, c = idx & 31;
        int row = tileBase + r;
        float4 v = make_float4(0.f, 0.f, 0.f, 0.f);
        if (row < nrows) v = ((const float4*)(A0 + (size_t)row * DD))[c];
        ((float4*)(As + r * 256))[c] = v;
    }

    // gather-max into As[r][128..255]  (H >= 0, init 0 exact)
    #pragma unroll
    for (int r = 0; r < 8; r++) {
        int row = tileBase + ty * 8 + r;
        float4 m = make_float4(0.f, 0.f, 0.f, 0.f);
        if (row < nrows) {
            const int* ip = nidx + (size_t)row * SS;
            int myi = (tx < SS) ? ip[tx] : 0;
            #pragma unroll
            for (int s = 0; s < SS; s++) {
                int j = __shfl_sync(0xffffffffu, myi, s);
                float4 v = ((const float4*)(H + (size_t)j * DD))[tx];
                m.x = fmaxf(m.x, v.x);
                m.y = fmaxf(m.y, v.y);
                m.z = fmaxf(m.z, v.z);
                m.w = fmaxf(m.w, v.w);
            }
        }
        ((float4*)(As + (ty * 8 + r) * 256 + 128))[tx] = m;
    }
    __syncthreads();

    u64 acc[8][4];
    #pragma unroll
    for (int r = 0; r < 8; r++)
        #pragma unroll
        for (int c = 0; c < 4; c++) acc[r][c] = 0ull;

    const float* Abase = As + (ty * 8) * 256;
    const float* Wl = Wt + (tx * 4) * 256;

    #pragma unroll 2
    for (int k = 0; k < 256; k += 4) {
        int slot = (((k >> 2) + tx) & 63) << 2;
        float4 w[4];
        #pragma unroll
        for (int c = 0; c < 4; c++)
            w[c] = *(const float4*)(Wl + c * 256 + slot);
        #pragma unroll
        for (int r = 0; r < 8; r++) {
            float4 a = *(const float4*)(Abase + r * 256 + k);
            u64 aL = lo64(a), aH = hi64(a);
            #pragma unroll
            for (int c = 0; c < 4; c++) {
                fma2(acc[r][c], aL, lo64(w[c]));
                fma2(acc[r][c], aH, hi64(w[c]));
            }
        }
    }

    float4 b4 = ((const float4*)bias)[tx];
    float cs[4] = {0.f, 0.f, 0.f, 0.f};
    float cq[4] = {0.f, 0.f, 0.f, 0.f};
    #pragma unroll
    for (int r = 0; r < 8; r++) {
        int row = tileBase + ty * 8 + r;
        if (row < nrows) {
            float2 p0 = upk2(acc[r][0]);
            float2 p1 = upk2(acc[r][1]);
            float2 p2 = upk2(acc[r][2]);
            float2 p3 = upk2(acc[r][3]);
            float4 o;
            o.x = p0.x + p0.y + b4.x;
            o.y = p1.x + p1.y + b4.y;
            o.z = p2.x + p2.y + b4.z;
            o.w = p3.x + p3.y + b4.w;
            if (RELU) {
                o.x = fmaxf(o.x, 0.f); o.y = fmaxf(o.y, 0.f);
                o.z = fmaxf(o.z, 0.f); o.w = fmaxf(o.w, 0.f);
            }
            ((float4*)(O + (size_t)row * DD))[tx] = o;
            if (BNSTATS) {
                cs[0] += o.x; cs[1] += o.y; cs[2] += o.z; cs[3] += o.w;
                cq[0] += o.x * o.x; cq[1] += o.y * o.y;
                cq[2] += o.z * o.z; cq[3] += o.w * o.w;
            }
        }
    }

    if (BNSTATS) {
        __syncthreads();               // done reading smem; reuse for reduction
        float* red = As;
        #pragma unroll
        for (int c = 0; c < 4; c++) {
            red[ty * 128 + tx * 4 + c]        = cs[c];
            red[1024 + ty * 128 + tx * 4 + c] = cq[c];
        }
        __syncthreads();
        if (tid < 128) {
            float s = 0.f, q = 0.f;
            #pragma unroll
            for (int w = 0; w < 8; w++) {
                s += red[w * 128 + tid];
                q += red[1024 + w * 128 + tid];
            }
            g_psum  [blockIdx.x * DD + tid] = s;
            g_psumsq[blockIdx.x * DD + tid] = q;
        }
    }
}

// ---------------------------------------------------------------------------
__global__ __launch_bounds__(1024) void bn_finalize(
    const float* __restrict__ gamma, const float* __restrict__ beta)
{
    __shared__ float rs[1024], rq[1024];
    const int t = threadIdx.x;
    const int col = t & 127, part = t >> 7;

    float s = 0.f, q = 0.f;
    for (int i = part; i < NBLK; i += 8) {
        s += g_psum  [i * DD + col];
        q += g_psumsq[i * DD + col];
    }
    rs[part * 128 + col] = s;
    rq[part * 128 + col] = q;
    __syncthreads();

    if (t < 128) {
        float ss = 0.f, qq = 0.f;
        #pragma unroll
        for (int p = 0; p < 8; p++) {
            ss += rs[p * 128 + t];
            qq += rq[p * 128 + t];
        }
        float mean = ss * (1.0f / NN);
        float var  = qq * (1.0f / NN) - mean * mean;
        float sc   = gamma[t] * rsqrtf(var + 1e-5f);
        g_scale[t] = sc;
        g_shift[t] = beta[t] - mean * sc;
    }
}

// ---------------------------------------------------------------------------
__global__ __launch_bounds__(256) void bn_rownorm(
    const float* __restrict__ X, float* __restrict__ XN, int nrows)
{
    const int ty = threadIdx.x >> 5, tx = threadIdx.x & 31;
    const int row = blockIdx.x * 8 + ty;
    if (row >= nrows) return;

    float4 v  = ((const float4*)(X + (size_t)row * DD))[tx];
    float4 sc = ((const float4*)g_scale)[tx];
    float4 sh = ((const float4*)g_shift)[tx];
    v.x = fmaf(v.x, sc.x, sh.x);
    v.y = fmaf(v.y, sc.y, sh.y);
    v.z = fmaf(v.z, sc.z, sh.z);
    v.w = fmaf(v.w, sc.w, sh.w);

    float ss = v.x * v.x + v.y * v.y + v.z * v.z + v.w * v.w;
    #pragma unroll
    for (int off = 16; off > 0; off >>= 1)
        ss += __shfl_xor_sync(0xffffffffu, ss, off);

    float inv = 1.0f / (sqrtf(ss) + 1e-6f);
    v.x *= inv; v.y *= inv; v.z *= inv; v.w *= inv;
    ((float4*)(XN + (size_t)row * DD))[tx] = v;
}

// ---------------------------------------------------------------------------
extern "C" void kernel_launch(void* const* d_in, const int* in_sizes, int n_in,
                              void* d_out, int out_size)
{
    const float* features = (const float*)d_in[0];
    const int*   idx1     = (const int*)  d_in[1];
    const int*   idx2     = (const int*)  d_in[2];
    const float* agg1_W   = (const float*)d_in[3];
    const float* agg1_b   = (const float*)d_in[4];
    const float* fc1_W    = (const float*)d_in[5];
    const float* fc1_b    = (const float*)d_in[6];
    const float* agg2_W   = (const float*)d_in[7];
    const float* agg2_b   = (const float*)d_in[8];
    const float* fc2_W    = (const float*)d_in[9];
    const float* fc2_b    = (const float*)d_in[10];
    const float* gamma    = (const float*)d_in[11];
    const float* beta     = (const float*)d_in[12];
    float* out = (float*)d_out;

    const int smem128 = (128 * 128 + TM * 128) * (int)sizeof(float);  //  98304
    const int smem256 = (128 * 256 + TM * 256) * (int)sizeof(float);  // 196608
    cudaFuncSetAttribute(gemm128_relu,
        cudaFuncAttributeMaxDynamicSharedMemorySize, smem128);
    cudaFuncSetAttribute(gather_gemm256<true, true>,
        cudaFuncAttributeMaxDynamicSharedMemorySize, smem256);
    cudaFuncSetAttribute(gather_gemm256<false, false>,
        cudaFuncAttributeMaxDynamicSharedMemorySize, smem256);

    float *h1, *x, *xn, *h2;
    cudaGetSymbolAddress((void**)&h1, g_h1);
    cudaGetSymbolAddress((void**)&x,  g_x);
    cudaGetSymbolAddress((void**)&xn, g_xn);
    cudaGetSymbolAddress((void**)&h2, g_h2);

    // ---- layer 1 ----
    gemm128_relu<<<NBLK, 256, smem128>>>(features, agg1_W, agg1_b, h1, NN);
    gather_gemm256<true, true><<<NBLK, 256, smem256>>>(
        features, h1, idx1, fc1_W, fc1_b, x, NN);
    bn_finalize<<<1, 1024>>>(gamma, beta);
    bn_rownorm<<<(NN + 7) / 8, 256>>>(x, xn, NN);

    // ---- layer 2 ----
    gemm128_relu<<<NBLK, 256, smem128>>>(xn, agg2_W, agg2_b, h2, NN);
    gather_gemm256<false, false><<<NBLK, 256, smem256>>>(
        xn, h2, idx2, fc2_W, fc2_b, out, NN);
}